// round 12
// baseline (speedup 1.0000x reference)
#include <cuda_runtime.h>

#define NG 2048
#define NU 16
#define NB 50
#define ND 64
#define FACTOR 0.5f

__global__ __launch_bounds__(256, 5)
void group_embedding_kernel(
    const int*   __restrict__ group_users,   // [G,U]
    const int*   __restrict__ user_lens,     // [G]
    const int*   __restrict__ beh_ids,       // [G,U,B]
    const float* __restrict__ beh_counts,    // [G,U,B]
    const int*   __restrict__ target_user,   // [G]
    const float* __restrict__ user_table,    // [N_USERS, D]
    const float* __restrict__ item_table,    // [N_ITEMS, D]
    const float* __restrict__ sim_vec,       // [N_USERS, D]
    const float* __restrict__ Wq, const float* __restrict__ bq,
    const float* __restrict__ Wk, const float* __restrict__ bk,
    const float* __restrict__ Wv, const float* __restrict__ bv,
    float*       __restrict__ out)           // [G, D]
{
    __shared__ float sTsim[ND];
    __shared__ float sQ[ND];
    __shared__ float sR[ND];           // r = Wk^T Q
    __shared__ float sLogit[NU];
    __shared__ float sWt[NU];
    __shared__ int   sGid[NU];
    __shared__ __align__(16) int   sIds[NU * NB];
    __shared__ __align__(16) float sCoef[NU * NB];
    __shared__ __align__(16) float sSim[NU][ND];
    __shared__ float sPool[16][ND];
    __shared__ float sPooled[ND];
    __shared__ float sQbkSum;

    const int g    = blockIdx.x;
    const int tid  = threadIdx.x;
    const int team = tid >> 4;      // 0..15
    const int lane = tid & 15;      // 0..15

    int L = user_lens[g];
    if (L < 1)  L = 1;
    if (L > NU) L = NU;

    const int total = L * NB;
    const size_t base = (size_t)g * NU * NB;

    // ---- Phase 0: one giant independent staging batch ----
    {
        const int nvec = total >> 2;
        const int4*   idv  = (const int4*)(beh_ids + base);
        const float4* cntv = (const float4*)(beh_counts + base);
        for (int i = tid; i < nvec; i += 256) {
            ((int4*)sIds)[i]    = __ldcs(idv + i);
            ((float4*)sCoef)[i] = __ldcs(cntv + i);
        }
        for (int i = (nvec << 2) + tid; i < total; i += 256) {
            sIds[i]  = __ldcs(beh_ids + base + i);
            sCoef[i] = __ldcs(beh_counts + base + i);
        }
    }
    if (tid < ND) sTsim[tid] = __ldcs(sim_vec + (size_t)target_user[g] * ND + tid);
    if (tid >= 64 && tid < 64 + NU) sGid[tid - 64] = __ldg(group_users + g * NU + (tid - 64));
    // sim rows for the logit phase (consumed AFTER the gather)
    for (int i = tid; i < L * ND; i += 256) {
        int r = i >> 6, d = i & 63;
        int gid = __ldg(group_users + g * NU + r);
        sSim[r][d] = __ldcs(sim_vec + (size_t)gid * ND + d);
    }
    __syncthreads();

    // ---- Phase 1: UNWEIGHTED per-user gather (no softmax dependency!) ----
    // team u accumulates u_emb[u] + sum_b count_b * item_b   (u < L)
    float4 acc  = make_float4(0.f, 0.f, 0.f, 0.f);
    float4 acc2 = make_float4(0.f, 0.f, 0.f, 0.f);
    if (team < L) {
        const float4* ur = (const float4*)(user_table + (size_t)sGid[team] * ND);
        acc = __ldcs(ur + lane);
        const int b0 = team * NB;
        #pragma unroll 2
        for (int j = 0; j < NB; j += 2) {
            float c0 = sCoef[b0 + j];
            float c1 = sCoef[b0 + j + 1];
            int   d0 = sIds[b0 + j];
            int   d1 = sIds[b0 + j + 1];
            if (c0 != 0.f) {
                float4 v = __ldg((const float4*)(item_table + (size_t)d0 * ND) + lane);
                acc.x += c0 * v.x; acc.y += c0 * v.y; acc.z += c0 * v.z; acc.w += c0 * v.w;
            }
            if (c1 != 0.f) {
                float4 v = __ldg((const float4*)(item_table + (size_t)d1 * ND) + lane);
                acc2.x += c1 * v.x; acc2.y += c1 * v.y; acc2.z += c1 * v.z; acc2.w += c1 * v.w;
            }
        }
        acc.x += acc2.x; acc.y += acc2.y; acc.z += acc2.z; acc.w += acc2.w;
    }
    ((float4*)&sPool[team][0])[lane] = acc;   // invalid teams store zeros

    // ---- Phase 2 (post-gather, smem-only inputs): Q = Wq @ tsim + bq ----
    // No sync needed yet: sTsim ready since Phase 0; sQ not read before next sync.
    {
        int d = tid >> 2, q = tid & 3;
        const float4* w4 = (const float4*)(Wq + d * ND + q * 16);
        const float*  s  = sTsim + q * 16;
        float p = 0.f;
        #pragma unroll
        for (int v = 0; v < 4; v++) {
            float4 w = __ldg(w4 + v);
            p += w.x * s[v*4+0] + w.y * s[v*4+1] + w.z * s[v*4+2] + w.w * s[v*4+3];
        }
        p += __shfl_xor_sync(0xffffffffu, p, 1);
        p += __shfl_xor_sync(0xffffffffu, p, 2);
        if (q == 0) sQ[d] = p + __ldg(bq + d);
    }
    __syncthreads();

    // ---- r = Wk^T Q; warp 2 computes Q.bk ----
    if (tid < ND) {
        float rr = 0.f;
        #pragma unroll 16
        for (int d = 0; d < ND; d++) rr += sQ[d] * __ldg(Wk + d * ND + tid);
        sR[tid] = rr;
    }
    if (tid >= 64 && tid < 96) {
        int t = tid - 64;
        float p = sQ[t] * __ldg(bk + t) + sQ[t + 32] * __ldg(bk + t + 32);
        #pragma unroll
        for (int off = 16; off; off >>= 1)
            p += __shfl_xor_sync(0xffffffffu, p, off);
        if (t == 0) sQbkSum = p;
    }
    __syncthreads();

    // ---- logits from smem sim rows ----
    {
        const float4* sv4 = (const float4*)&sSim[(team < L) ? team : 0][0];
        float4 sv = sv4[lane];
        const float* r4 = sR + lane * 4;
        float part = r4[0] * sv.x + r4[1] * sv.y + r4[2] * sv.z + r4[3] * sv.w;
        #pragma unroll
        for (int off = 8; off; off >>= 1)
            part += __shfl_xor_sync(0xffffffffu, part, off, 16);
        if (lane == 0) sLogit[team] = FACTOR * (part + sQbkSum);
    }
    __syncthreads();

    // ---- masked softmax over the L users (warp 0) ----
    if (tid < 32) {
        int u = tid & 15;
        float v = (u < L) ? sLogit[u] : -3.402823466e38f;
        float m = v;
        #pragma unroll
        for (int off = 8; off; off >>= 1)
            m = fmaxf(m, __shfl_xor_sync(0xffffffffu, m, off, 16));
        float e = (u < L) ? __expf(v - m) : 0.f;
        float s = e;
        #pragma unroll
        for (int off = 8; off; off >>= 1)
            s += __shfl_xor_sync(0xffffffffu, s, off, 16);
        if (tid < 16) sWt[u] = e / s;    // exactly 0 for invalid users
    }
    __syncthreads();

    // ---- WEIGHTED reduce of the 16 per-user accumulators ----
    if (tid < ND) {
        float s = 0.f;
        #pragma unroll
        for (int t = 0; t < 16; t++) s += sWt[t] * sPool[t][tid];
        sPooled[tid] = s;
    }
    __syncthreads();

    // ---- out = Wv @ pooled + bv : 4 threads/row, float4 ----
    {
        int d = tid >> 2, q = tid & 3;
        const float4* w4 = (const float4*)(Wv + d * ND + q * 16);
        const float*  s  = sPooled + q * 16;
        float p = 0.f;
        #pragma unroll
        for (int v = 0; v < 4; v++) {
            float4 w = __ldg(w4 + v);
            p += w.x * s[v*4+0] + w.y * s[v*4+1] + w.z * s[v*4+2] + w.w * s[v*4+3];
        }
        p += __shfl_xor_sync(0xffffffffu, p, 1);
        p += __shfl_xor_sync(0xffffffffu, p, 2);
        if (q == 0) __stcs(out + (size_t)g * ND + d, p + __ldg(bv + d));
    }
}

extern "C" void kernel_launch(void* const* d_in, const int* in_sizes, int n_in,
                              void* d_out, int out_size)
{
    const int*   group_users = (const int*)  d_in[0];
    const int*   user_lens   = (const int*)  d_in[1];
    const int*   beh_ids     = (const int*)  d_in[2];
    const float* beh_counts  = (const float*)d_in[3];
    const int*   target_user = (const int*)  d_in[4];
    const float* user_table  = (const float*)d_in[5];
    const float* item_table  = (const float*)d_in[6];
    const float* sim_vec     = (const float*)d_in[7];
    const float* Wq          = (const float*)d_in[8];
    const float* bq          = (const float*)d_in[9];
    const float* Wk          = (const float*)d_in[10];
    const float* bk          = (const float*)d_in[11];
    const float* Wv          = (const float*)d_in[12];
    const float* bv          = (const float*)d_in[13];
    float*       out         = (float*)d_out;

    group_embedding_kernel<<<NG, 256>>>(
        group_users, user_lens, beh_ids, beh_counts, target_user,
        user_table, item_table, sim_vec,
        Wq, bq, Wk, bk, Wv, bv, out);
}

// round 13
// speedup vs baseline: 1.1629x; 1.1629x over previous
#include <cuda_runtime.h>

#define NG 2048
#define NU 16
#define NB 50
#define ND 64
#define FACTOR 0.5f

__global__ __launch_bounds__(256, 6)
void group_embedding_kernel(
    const int*   __restrict__ group_users,   // [G,U]
    const int*   __restrict__ user_lens,     // [G]
    const int*   __restrict__ beh_ids,       // [G,U,B]
    const float* __restrict__ beh_counts,    // [G,U,B]
    const int*   __restrict__ target_user,   // [G]
    const float* __restrict__ user_table,    // [N_USERS, D]
    const float* __restrict__ item_table,    // [N_ITEMS, D]
    const float* __restrict__ sim_vec,       // [N_USERS, D]
    const float* __restrict__ Wq, const float* __restrict__ bq,
    const float* __restrict__ Wk, const float* __restrict__ bk,
    const float* __restrict__ Wv, const float* __restrict__ bv,
    float*       __restrict__ out)           // [G, D]
{
    __shared__ float sTsim[ND];
    __shared__ float sQ[ND];
    __shared__ float sR[ND];           // r = Wk^T Q
    __shared__ float sLogit[NU];
    __shared__ float sWt[NU];
    __shared__ float sWtTeam[16];
    __shared__ int   sGid[NU];
    __shared__ __align__(16) int   sIds[NU * NB];
    __shared__ __align__(16) float sCoef[NU * NB];
    __shared__ __align__(16) float sSim[NU][ND];
    __shared__ float sPool[16][ND];
    __shared__ float sPooled[ND];
    __shared__ float sQbkSum;

    const int g    = blockIdx.x;
    const int tid  = threadIdx.x;
    const int team = tid >> 4;      // 0..15
    const int lane = tid & 15;      // 0..15

    int L = user_lens[g];
    if (L < 1)  L = 1;
    if (L > NU) L = NU;

    const int total = L * NB;
    const size_t base = (size_t)g * NU * NB;

    // ---- Phase 0: one giant independent staging batch ----
    {
        const int nvec = total >> 2;
        const int4*   idv  = (const int4*)(beh_ids + base);
        const float4* cntv = (const float4*)(beh_counts + base);
        for (int i = tid; i < nvec; i += 256) {
            ((int4*)sIds)[i]    = __ldcs(idv + i);
            ((float4*)sCoef)[i] = __ldcs(cntv + i);
        }
        for (int i = (nvec << 2) + tid; i < total; i += 256) {
            sIds[i]  = __ldcs(beh_ids + base + i);
            sCoef[i] = __ldcs(beh_counts + base + i);
        }
    }
    if (tid < ND) sTsim[tid] = __ldcs(sim_vec + (size_t)target_user[g] * ND + tid);
    if (tid >= 64 && tid < 64 + NU) sGid[tid - 64] = __ldg(group_users + g * NU + (tid - 64));
    // sim rows for the logit phase (consumed after the gather is in flight)
    for (int i = tid; i < L * ND; i += 256) {
        int r = i >> 6, d = i & 63;
        int gid = __ldg(group_users + g * NU + r);
        sSim[r][d] = __ldcs(sim_vec + (size_t)gid * ND + d);
    }
    __syncthreads();

    // ---- Phase 1: UNWEIGHTED gather, multi-team-per-user (balanced) ----
    // team t serves user u = t%L as worker k = t/L of n = (15-u)/L + 1 workers.
    float4 acc = make_float4(0.f, 0.f, 0.f, 0.f);
    {
        const int u = team % L;
        const int k = team / L;
        const int n = (15 - u) / L + 1;
        const int b0 = u * NB;
        if (k == 0) {   // worker 0 seeds with the (unweighted) user embedding
            const float4* ur = (const float4*)(user_table + (size_t)sGid[u] * ND);
            acc = __ldcs(ur + lane);
        }
        #pragma unroll 4
        for (int j = k; j < NB; j += n) {
            float c = sCoef[b0 + j];
            if (c != 0.f) {
                const float4* row = (const float4*)(item_table + (size_t)sIds[b0 + j] * ND);
                float4 v = __ldg(row + lane);
                acc.x += c * v.x; acc.y += c * v.y; acc.z += c * v.z; acc.w += c * v.w;
            }
        }
    }
    ((float4*)&sPool[team][0])[lane] = acc;

    // ---- Phase 2 (runs after gather issues; inputs smem-resident): Q ----
    {
        int d = tid >> 2, q = tid & 3;
        const float4* w4 = (const float4*)(Wq + d * ND + q * 16);
        const float*  s  = sTsim + q * 16;
        float p = 0.f;
        #pragma unroll
        for (int v = 0; v < 4; v++) {
            float4 w = __ldg(w4 + v);
            p += w.x * s[v*4+0] + w.y * s[v*4+1] + w.z * s[v*4+2] + w.w * s[v*4+3];
        }
        p += __shfl_xor_sync(0xffffffffu, p, 1);
        p += __shfl_xor_sync(0xffffffffu, p, 2);
        if (q == 0) sQ[d] = p + __ldg(bq + d);
    }
    __syncthreads();

    // ---- r = Wk^T Q; warp 2 computes Q.bk ----
    if (tid < ND) {
        float rr = 0.f;
        #pragma unroll 16
        for (int d = 0; d < ND; d++) rr += sQ[d] * __ldg(Wk + d * ND + tid);
        sR[tid] = rr;
    }
    if (tid >= 64 && tid < 96) {
        int t = tid - 64;
        float p = sQ[t] * __ldg(bk + t) + sQ[t + 32] * __ldg(bk + t + 32);
        #pragma unroll
        for (int off = 16; off; off >>= 1)
            p += __shfl_xor_sync(0xffffffffu, p, off);
        if (t == 0) sQbkSum = p;
    }
    __syncthreads();

    // ---- logits from smem sim rows ----
    {
        const float4* sv4 = (const float4*)&sSim[(team < L) ? team : 0][0];
        float4 sv = sv4[lane];
        const float* r4 = sR + lane * 4;
        float part = r4[0] * sv.x + r4[1] * sv.y + r4[2] * sv.z + r4[3] * sv.w;
        #pragma unroll
        for (int off = 8; off; off >>= 1)
            part += __shfl_xor_sync(0xffffffffu, part, off, 16);
        if (lane == 0) sLogit[team] = FACTOR * (part + sQbkSum);
    }
    __syncthreads();

    // ---- masked softmax (warp 0), then per-team weight table ----
    if (tid < 32) {
        int u = tid & 15;
        float v = (u < L) ? sLogit[u] : -3.402823466e38f;
        float m = v;
        #pragma unroll
        for (int off = 8; off; off >>= 1)
            m = fmaxf(m, __shfl_xor_sync(0xffffffffu, m, off, 16));
        float e = (u < L) ? __expf(v - m) : 0.f;
        float s = e;
        #pragma unroll
        for (int off = 8; off; off >>= 1)
            s += __shfl_xor_sync(0xffffffffu, s, off, 16);
        if (tid < 16) sWt[u] = e / s;
    }
    __syncthreads();
    if (tid < 16) sWtTeam[tid] = sWt[tid % L];
    __syncthreads();

    // ---- WEIGHTED reduce of the 16 disjoint partial sums ----
    if (tid < ND) {
        float s = 0.f;
        #pragma unroll
        for (int t = 0; t < 16; t++) s += sWtTeam[t] * sPool[t][tid];
        sPooled[tid] = s;
    }
    __syncthreads();

    // ---- out = Wv @ pooled + bv : 4 threads/row, float4 ----
    {
        int d = tid >> 2, q = tid & 3;
        const float4* w4 = (const float4*)(Wv + d * ND + q * 16);
        const float*  s  = sPooled + q * 16;
        float p = 0.f;
        #pragma unroll
        for (int v = 0; v < 4; v++) {
            float4 w = __ldg(w4 + v);
            p += w.x * s[v*4+0] + w.y * s[v*4+1] + w.z * s[v*4+2] + w.w * s[v*4+3];
        }
        p += __shfl_xor_sync(0xffffffffu, p, 1);
        p += __shfl_xor_sync(0xffffffffu, p, 2);
        if (q == 0) __stcs(out + (size_t)g * ND + d, p + __ldg(bv + d));
    }
}

extern "C" void kernel_launch(void* const* d_in, const int* in_sizes, int n_in,
                              void* d_out, int out_size)
{
    const int*   group_users = (const int*)  d_in[0];
    const int*   user_lens   = (const int*)  d_in[1];
    const int*   beh_ids     = (const int*)  d_in[2];
    const float* beh_counts  = (const float*)d_in[3];
    const int*   target_user = (const int*)  d_in[4];
    const float* user_table  = (const float*)d_in[5];
    const float* item_table  = (const float*)d_in[6];
    const float* sim_vec     = (const float*)d_in[7];
    const float* Wq          = (const float*)d_in[8];
    const float* bq          = (const float*)d_in[9];
    const float* Wk          = (const float*)d_in[10];
    const float* bk          = (const float*)d_in[11];
    const float* Wv          = (const float*)d_in[12];
    const float* bv          = (const float*)d_in[13];
    float*       out         = (float*)d_out;

    group_embedding_kernel<<<NG, 256>>>(
        group_users, user_lens, beh_ids, beh_counts, target_user,
        user_table, item_table, sim_vec,
        Wq, bq, Wk, bk, Wv, bv, out);
}

// round 14
// speedup vs baseline: 1.2766x; 1.0978x over previous
#include <cuda_runtime.h>

#define NG 2048
#define NU 16
#define NB 50
#define ND 64
#define FACTOR 0.5f

__global__ __launch_bounds__(256, 6)
void group_embedding_kernel(
    const int*   __restrict__ group_users,   // [G,U]
    const int*   __restrict__ user_lens,     // [G]
    const int*   __restrict__ beh_ids,       // [G,U,B]
    const float* __restrict__ beh_counts,    // [G,U,B]
    const int*   __restrict__ target_user,   // [G]
    const float* __restrict__ user_table,    // [N_USERS, D]
    const float* __restrict__ item_table,    // [N_ITEMS, D]
    const float* __restrict__ sim_vec,       // [N_USERS, D]
    const float* __restrict__ Wq, const float* __restrict__ bq,
    const float* __restrict__ Wk, const float* __restrict__ bk,
    const float* __restrict__ Wv, const float* __restrict__ bv,
    float*       __restrict__ out)           // [G, D]
{
    __shared__ float sTsim[ND];
    __shared__ float sQ[ND];
    __shared__ float sR[ND];           // r = Wk^T Q
    __shared__ float sLogit[NU];
    __shared__ float sWt[NU];
    __shared__ int   sGid[NU];
    __shared__ __align__(16) int   sIds[NU * NB];
    __shared__ __align__(16) float sCoef[NU * NB];
    __shared__ float sPool[16][ND];
    __shared__ float sPooled[ND];
    __shared__ float sQbkSum;

    const int g    = blockIdx.x;
    const int tid  = threadIdx.x;
    const int team = tid >> 4;      // 0..15
    const int lane = tid & 15;      // 0..15

    int L = user_lens[g];
    if (L < 1)  L = 1;
    if (L > NU) L = NU;

    const int total = L * NB;
    const size_t base = (size_t)g * NU * NB;

    // ---- Phase 0: one giant independent staging batch (max DRAM MLP up front) ----
    {
        const int nvec = total >> 2;
        const int4*   idv  = (const int4*)(beh_ids + base);
        const float4* cntv = (const float4*)(beh_counts + base);
        for (int i = tid; i < nvec; i += 256) {
            ((int4*)sIds)[i]    = __ldcs(idv + i);
            ((float4*)sCoef)[i] = __ldcs(cntv + i);
        }
        for (int i = (nvec << 2) + tid; i < total; i += 256) {
            sIds[i]  = __ldcs(beh_ids + base + i);
            sCoef[i] = __ldcs(beh_counts + base + i);
        }
    }
    if (tid < ND) sTsim[tid] = __ldcs(sim_vec + (size_t)target_user[g] * ND + tid);
    if (tid >= 64 && tid < 64 + NU) sGid[tid - 64] = __ldg(group_users + g * NU + (tid - 64));
    __syncthreads();

    // ---- Q = Wq @ Tsim + bq : 4 threads/row, 4x float4 loads each ----
    {
        int d = tid >> 2, q = tid & 3;
        const float4* w4 = (const float4*)(Wq + d * ND + q * 16);
        const float*  s  = sTsim + q * 16;
        float p = 0.f;
        #pragma unroll
        for (int v = 0; v < 4; v++) {
            float4 w = __ldg(w4 + v);
            p += w.x * s[v*4+0] + w.y * s[v*4+1] + w.z * s[v*4+2] + w.w * s[v*4+3];
        }
        p += __shfl_xor_sync(0xffffffffu, p, 1);
        p += __shfl_xor_sync(0xffffffffu, p, 2);
        if (q == 0) sQ[d] = p + __ldg(bq + d);
    }
    __syncthreads();

    // ---- r = Wk^T Q (coalesced columns); warp 2 computes Q.bk ----
    if (tid < ND) {
        float rr = 0.f;
        #pragma unroll 16
        for (int d = 0; d < ND; d++) rr += sQ[d] * __ldg(Wk + d * ND + tid);
        sR[tid] = rr;
    }
    if (tid >= 64 && tid < 96) {
        int t = tid - 64;
        float p = sQ[t] * __ldg(bk + t) + sQ[t + 32] * __ldg(bk + t + 32);
        #pragma unroll
        for (int off = 16; off; off >>= 1)
            p += __shfl_xor_sync(0xffffffffu, p, off);
        if (t == 0) sQbkSum = p;
    }
    __syncthreads();

    // ---- logit[u] = FACTOR * (r . sim_u + Q.bk): team u streams its sim row ----
    {
        int uu = (team < L) ? team : 0;
        const float4* srow = (const float4*)(sim_vec + (size_t)sGid[uu] * ND);
        float4 sv = __ldcs(srow + lane);
        const float* r4 = sR + lane * 4;
        float part = r4[0] * sv.x + r4[1] * sv.y + r4[2] * sv.z + r4[3] * sv.w;
        #pragma unroll
        for (int off = 8; off; off >>= 1)
            part += __shfl_xor_sync(0xffffffffu, part, off, 16);
        if (lane == 0) sLogit[team] = FACTOR * (part + sQbkSum);
    }
    __syncthreads();

    // ---- masked softmax over the L users (warp 0) ----
    if (tid < 32) {
        int u = tid & 15;
        float v = (u < L) ? sLogit[u] : -3.402823466e38f;
        float m = v;
        #pragma unroll
        for (int off = 8; off; off >>= 1)
            m = fmaxf(m, __shfl_xor_sync(0xffffffffu, m, off, 16));
        float e = (u < L) ? __expf(v - m) : 0.f;
        float s = e;
        #pragma unroll
        for (int off = 8; off; off >>= 1)
            s += __shfl_xor_sync(0xffffffffu, s, off, 16);
        if (tid < 16) sWt[u] = e / s;
    }
    __syncthreads();

    // ---- load-balanced weighted gather-sum (team-strided, R8 shape);
    //      weight folded in-loop: u = i/50 via (i*5243)>>18 (exact for i<12k) ----
    float4 acc = make_float4(0.f, 0.f, 0.f, 0.f);
    if (team < L) {
        float wgt = sWt[team];
        const float4* ur = (const float4*)(user_table + (size_t)sGid[team] * ND);
        float4 v = __ldcs(ur + lane);
        acc.x = wgt * v.x; acc.y = wgt * v.y; acc.z = wgt * v.z; acc.w = wgt * v.w;
    }
    #pragma unroll 4
    for (int i = team; i < total; i += 16) {
        float cnt = sCoef[i];
        if (cnt != 0.f) {
            float c = cnt * sWt[(i * 5243) >> 18];
            const float4* row = (const float4*)(item_table + (size_t)sIds[i] * ND);
            float4 v = __ldg(row + lane);
            acc.x += c * v.x; acc.y += c * v.y; acc.z += c * v.z; acc.w += c * v.w;
        }
    }
    ((float4*)&sPool[team][0])[lane] = acc;
    __syncthreads();

    // ---- reduce the 16 team accumulators ----
    if (tid < ND) {
        float s = 0.f;
        #pragma unroll
        for (int t = 0; t < 16; t++) s += sPool[t][tid];
        sPooled[tid] = s;
    }
    __syncthreads();

    // ---- out = Wv @ pooled + bv : 4 threads/row, 4x float4 loads ----
    {
        int d = tid >> 2, q = tid & 3;
        const float4* w4 = (const float4*)(Wv + d * ND + q * 16);
        const float*  s  = sPooled + q * 16;
        float p = 0.f;
        #pragma unroll
        for (int v = 0; v < 4; v++) {
            float4 w = __ldg(w4 + v);
            p += w.x * s[v*4+0] + w.y * s[v*4+1] + w.z * s[v*4+2] + w.w * s[v*4+3];
        }
        p += __shfl_xor_sync(0xffffffffu, p, 1);
        p += __shfl_xor_sync(0xffffffffu, p, 2);
        if (q == 0) __stcs(out + (size_t)g * ND + d, p + __ldg(bv + d));
    }
}

extern "C" void kernel_launch(void* const* d_in, const int* in_sizes, int n_in,
                              void* d_out, int out_size)
{
    const int*   group_users = (const int*)  d_in[0];
    const int*   user_lens   = (const int*)  d_in[1];
    const int*   beh_ids     = (const int*)  d_in[2];
    const float* beh_counts  = (const float*)d_in[3];
    const int*   target_user = (const int*)  d_in[4];
    const float* user_table  = (const float*)d_in[5];
    const float* item_table  = (const float*)d_in[6];
    const float* sim_vec     = (const float*)d_in[7];
    const float* Wq          = (const float*)d_in[8];
    const float* bq          = (const float*)d_in[9];
    const float* Wk          = (const float*)d_in[10];
    const float* bk          = (const float*)d_in[11];
    const float* Wv          = (const float*)d_in[12];
    const float* bv          = (const float*)d_in[13];
    float*       out         = (float*)d_out;

    group_embedding_kernel<<<NG, 256>>>(
        group_users, user_lens, beh_ids, beh_counts, target_user,
        user_table, item_table, sim_vec,
        Wq, bq, Wk, bk, Wv, bv, out);
}

// round 15
// speedup vs baseline: 1.4498x; 1.1356x over previous
#include <cuda_runtime.h>

#define NG 2048
#define NU 16
#define NB 50
#define ND 64
#define FACTOR 0.5f

__global__ __launch_bounds__(256, 6)
void group_embedding_kernel(
    const int*   __restrict__ group_users,   // [G,U]
    const int*   __restrict__ user_lens,     // [G]
    const int*   __restrict__ beh_ids,       // [G,U,B]
    const float* __restrict__ beh_counts,    // [G,U,B]
    const int*   __restrict__ target_user,   // [G]
    const float* __restrict__ user_table,    // [N_USERS, D]
    const float* __restrict__ item_table,    // [N_ITEMS, D]
    const float* __restrict__ sim_vec,       // [N_USERS, D]
    const float* __restrict__ Wq, const float* __restrict__ bq,
    const float* __restrict__ Wk, const float* __restrict__ bk,
    const float* __restrict__ Wv, const float* __restrict__ bv,
    float*       __restrict__ out)           // [G, D]
{
    __shared__ float sTsim[ND];
    __shared__ float sQ[ND];
    __shared__ float sR[ND];           // r = Wk^T Q
    __shared__ float sLogit[NU];
    __shared__ float sWt[NU];
    __shared__ int   sGid[NU];
    __shared__ __align__(16) int   sIds[NU * NB];
    __shared__ __align__(16) float sCoef[NU * NB];
    __shared__ float sPool[16][ND];
    __shared__ float sPooled[ND];
    __shared__ float sQbkSum;

    const int g    = blockIdx.x;
    const int tid  = threadIdx.x;
    const int team = tid >> 4;      // 0..15
    const int lane = tid & 15;      // 0..15

    int L = user_lens[g];
    if (L < 1)  L = 1;
    if (L > NU) L = NU;

    const int total = L * NB;
    const size_t base = (size_t)g * NU * NB;

    // ---- Phase 0: kick off ALL independent streaming loads first ----
    {
        const int nvec = total >> 2;
        const int4*   idv  = (const int4*)(beh_ids + base);
        const float4* cntv = (const float4*)(beh_counts + base);
        for (int i = tid; i < nvec; i += 256) {
            int4   iv = __ldcs(idv + i);
            float4 cv = __ldcs(cntv + i);
            ((int4*)sIds)[i]    = iv;
            ((float4*)sCoef)[i] = cv;
        }
        for (int i = (nvec << 2) + tid; i < total; i += 256) {
            sIds[i]  = __ldcs(beh_ids + base + i);
            sCoef[i] = __ldcs(beh_counts + base + i);
        }
    }
    if (tid < ND) sTsim[tid] = __ldcs(sim_vec + (size_t)target_user[g] * ND + tid);
    if (tid >= 64 && tid < 64 + NU) sGid[tid - 64] = __ldcs(group_users + g * NU + (tid - 64));
    __syncthreads();

    // ---- Q = Wq @ Tsim + bq : 4 threads/row, 4x float4 loads each ----
    {
        int d = tid >> 2, q = tid & 3;
        const float4* w4 = (const float4*)(Wq + d * ND + q * 16);
        const float*  s  = sTsim + q * 16;
        float p = 0.f;
        #pragma unroll
        for (int v = 0; v < 4; v++) {
            float4 w = __ldg(w4 + v);
            p += w.x * s[v*4+0] + w.y * s[v*4+1] + w.z * s[v*4+2] + w.w * s[v*4+3];
        }
        p += __shfl_xor_sync(0xffffffffu, p, 1);
        p += __shfl_xor_sync(0xffffffffu, p, 2);
        if (q == 0) sQ[d] = p + __ldg(bq + d);
    }
    __syncthreads();

    // ---- r = Wk^T Q (coalesced columns); warp 2 computes Q.bk ----
    if (tid < ND) {
        float rr = 0.f;
        #pragma unroll 16
        for (int d = 0; d < ND; d++) rr += sQ[d] * __ldg(Wk + d * ND + tid);
        sR[tid] = rr;
    }
    if (tid >= 64 && tid < 96) {
        int t = tid - 64;
        float p = sQ[t] * __ldg(bk + t) + sQ[t + 32] * __ldg(bk + t + 32);
        #pragma unroll
        for (int off = 16; off; off >>= 1)
            p += __shfl_xor_sync(0xffffffffu, p, off);
        if (t == 0) sQbkSum = p;
    }
    __syncthreads();

    // ---- logit[u] = FACTOR * (r . sim_u + Q.bk): team u streams its sim row ----
    {
        int uu = (team < L) ? team : 0;
        const float4* srow = (const float4*)(sim_vec + (size_t)sGid[uu] * ND);
        float4 sv = __ldcs(srow + lane);
        const float* r4 = sR + lane * 4;
        float part = r4[0] * sv.x + r4[1] * sv.y + r4[2] * sv.z + r4[3] * sv.w;
        #pragma unroll
        for (int off = 8; off; off >>= 1)
            part += __shfl_xor_sync(0xffffffffu, part, off, 16);
        if (lane == 0) sLogit[team] = FACTOR * (part + sQbkSum);
    }
    __syncthreads();

    // ---- masked softmax over the L users (warp 0) ----
    if (tid < 32) {
        int u = tid & 15;
        float v = (u < L) ? sLogit[u] : -3.402823466e38f;
        float m = v;
        #pragma unroll
        for (int off = 8; off; off >>= 1)
            m = fmaxf(m, __shfl_xor_sync(0xffffffffu, m, off, 16));
        float e = (u < L) ? __expf(v - m) : 0.f;
        float s = e;
        #pragma unroll
        for (int off = 8; off; off >>= 1)
            s += __shfl_xor_sync(0xffffffffu, s, off, 16);
        if (tid < 16) sWt[u] = e / s;
    }
    __syncthreads();

    // ---- scale staged counts by attention weight ----
    for (int i = tid; i < total; i += 256) sCoef[i] *= sWt[i / NB];
    __syncthreads();

    // ---- load-balanced weighted gather-sum (team-strided; R3-proven loop) ----
    float4 acc = make_float4(0.f, 0.f, 0.f, 0.f);
    if (team < L) {
        float wgt = sWt[team];
        const float4* ur = (const float4*)(user_table + (size_t)sGid[team] * ND);
        float4 v = __ldcs(ur + lane);
        acc.x = wgt * v.x; acc.y = wgt * v.y; acc.z = wgt * v.z; acc.w = wgt * v.w;
    }
    #pragma unroll 4
    for (int i = team; i < total; i += 16) {
        float c = sCoef[i];
        if (c != 0.f) {
            const float4* row = (const float4*)(item_table + (size_t)sIds[i] * ND);
            float4 v = __ldg(row + lane);
            acc.x += c * v.x; acc.y += c * v.y; acc.z += c * v.z; acc.w += c * v.w;
        }
    }
    ((float4*)&sPool[team][0])[lane] = acc;
    __syncthreads();

    // ---- reduce the 16 team accumulators ----
    if (tid < ND) {
        float s = 0.f;
        #pragma unroll
        for (int t = 0; t < 16; t++) s += sPool[t][tid];
        sPooled[tid] = s;
    }
    __syncthreads();

    // ---- out = Wv @ pooled + bv : 4 threads/row, 4x float4 loads ----
    {
        int d = tid >> 2, q = tid & 3;
        const float4* w4 = (const float4*)(Wv + d * ND + q * 16);
        const float*  s  = sPooled + q * 16;
        float p = 0.f;
        #pragma unroll
        for (int v = 0; v < 4; v++) {
            float4 w = __ldg(w4 + v);
            p += w.x * s[v*4+0] + w.y * s[v*4+1] + w.z * s[v*4+2] + w.w * s[v*4+3];
        }
        p += __shfl_xor_sync(0xffffffffu, p, 1);
        p += __shfl_xor_sync(0xffffffffu, p, 2);
        if (q == 0) __stcs(out + (size_t)g * ND + d, p + __ldg(bv + d));
    }
}

extern "C" void kernel_launch(void* const* d_in, const int* in_sizes, int n_in,
                              void* d_out, int out_size)
{
    const int*   group_users = (const int*)  d_in[0];
    const int*   user_lens   = (const int*)  d_in[1];
    const int*   beh_ids     = (const int*)  d_in[2];
    const float* beh_counts  = (const float*)d_in[3];
    const int*   target_user = (const int*)  d_in[4];
    const float* user_table  = (const float*)d_in[5];
    const float* item_table  = (const float*)d_in[6];
    const float* sim_vec     = (const float*)d_in[7];
    const float* Wq          = (const float*)d_in[8];
    const float* bq          = (const float*)d_in[9];
    const float* Wk          = (const float*)d_in[10];
    const float* bk          = (const float*)d_in[11];
    const float* Wv          = (const float*)d_in[12];
    const float* bv          = (const float*)d_in[13];
    float*       out         = (float*)d_out;

    group_embedding_kernel<<<NG, 256>>>(
        group_users, user_lens, beh_ids, beh_counts, target_user,
        user_table, item_table, sim_vec,
        Wq, bq, Wk, bk, Wv, bv, out);
}